// round 13
// baseline (speedup 1.0000x reference)
#include <cuda_runtime.h>

// GCN_18760417149681 — fully linear GraphSAGE collapse, v13 (3 launches + PDL).
// out[m] = inv[m]*(SB[m] + SG[m]) + xs[m] + (deg[m]>0)*CB + C2
//   ACC[m] = (SA, deg, SG, xs);  scatter1: ACC[dst] += (xp[src], 1, xg[src], 0)
//   scatter2: SB[dst] += SA[src]/max(deg[src],1); last block writes out[].
// k_init = prep(block0) + edge decode (packed int2) + passA.

#define NMAX  100000
#define EMAX  1600000
#define NFEAT 64
#define NHID  128
#define SBLK  888        // one-wave scatter grid (6 blocks/SM x 148 SMs)

__device__ __align__(16) float g_P[NFEAT];
__device__ __align__(16) float g_G[NFEAT];
__device__ __align__(16) float g_S[NFEAT];
__device__ float g_C[2];        // [0]=cb (gated by deg>0), [1]=c2
__device__ int   g_ready = 0;   // prep-done flag (rewrites value-identical)
__device__ unsigned g_done = 0; // scatter2 completion ticket (self-resetting)

__device__ __align__(16) float4 g_ACC[NMAX];   // (SA, deg, SG, xs)
__device__ __align__(8)  float2 g_XPG[NMAX];   // (xp, xg)
__device__ float g_SB[NMAX];
__device__ __align__(16) int2  g_EDGE[EMAX];   // packed (src, dst)

// ---- dtype sniff: int64 LE small indices => odd 32-bit words all zero ----
__device__ __forceinline__ int sniff_is64(const int* __restrict__ ei32, int E)
{
    int odd_nonzero = 0;
    #pragma unroll 1
    for (int k = 0; k < 32; k++) {
        long long pos = (1 + (long long)k * ((2LL * E - 2) / 32)) | 1;
        if (ei32[pos] != 0) odd_nonzero++;
    }
    return (odd_nonzero == 0) ? 1 : 0;
}

// ===================== launch 1: prep + decode + passA =====================
__global__ void __launch_bounds__(256) k_init(
    const float* __restrict__ x, const int* __restrict__ ei32,
    const float* __restrict__ Wl1, const float* __restrict__ Wr1,
    const float* __restrict__ b1,
    const float* __restrict__ Wl2, const float* __restrict__ Wr2,
    const float* __restrict__ b2,
    const float* __restrict__ Wfc1, const float* __restrict__ bfc1,
    const float* __restrict__ Wfc2, const float* __restrict__ bfc2,
    int N, int E, int decBlocks)
{
    int b = blockIdx.x;
    int t = threadIdx.x;

    // -------- block 0: weight collapse --------
    if (b == 0) {
        __shared__ float sw[NHID], su[NHID], sv[NHID];
        if (t < NHID) {
            float acc = 0.f;
            #pragma unroll
            for (int c = 0; c < 32; c++) acc += Wfc1[t * 32 + c] * Wfc2[c];
            sw[t] = acc;
        }
        __syncthreads();
        if (t < NHID) {
            float au = 0.f, av = 0.f;
            #pragma unroll 4
            for (int j = 0; j < NHID; j++) {
                float wv = sw[j];
                au += Wl2[t * NHID + j] * wv;
                av += Wr2[t * NHID + j] * wv;
            }
            su[t] = au; sv[t] = av;
        }
        __syncthreads();
        if (t < NFEAT) {
            float p = 0.f, g = 0.f, s = 0.f;
            #pragma unroll 4
            for (int j = 0; j < NHID; j++) {
                float wl = Wl1[t * NHID + j];
                float wr = Wr1[t * NHID + j];
                float uj = su[j], vj = sv[j];
                p += wl * uj;
                g += wr * uj + wl * vj;
                s += wr * vj;
            }
            g_P[t] = p; g_G[t] = g; g_S[t] = s;
        }
        if (t == 0) {
            float cb = 0.f, c2 = 0.f;
            for (int j = 0; j < NHID; j++) {
                cb += b1[j] * su[j];
                c2 += b1[j] * sv[j] + b2[j] * sw[j];
            }
            for (int c = 0; c < 32; c++) c2 += bfc1[c] * Wfc2[c];
            c2 += bfc2[0];
            g_C[0] = cb; g_C[1] = c2;
        }
        __syncthreads();
        if (t == 0) {
            __threadfence();
            atomicExch(&g_ready, 1);
        }
        cudaTriggerProgrammaticLaunchCompletion();
        return;
    }

    // -------- blocks [1, decBlocks]: edge decode (no prep dependency) --------
    if (b <= decBlocks) {
        __shared__ int s_is64;
        if (t == 0) s_is64 = sniff_is64(ei32, E);
        __syncthreads();
        int is64 = s_is64;

        long long base = ((long long)(b - 1) * 256 + t) * 4;
        if (base < E) {
            if (base + 3 < E) {
                int s[4], d[4];
                if (is64) {
                    const long long* p = (const long long*)ei32;
                    longlong2 a = __ldg((const longlong2*)(p + base));
                    longlong2 c = __ldg((const longlong2*)(p + base + 2));
                    longlong2 e = __ldg((const longlong2*)(p + E + base));
                    longlong2 f = __ldg((const longlong2*)(p + E + base + 2));
                    s[0] = (int)a.x; s[1] = (int)a.y; s[2] = (int)c.x; s[3] = (int)c.y;
                    d[0] = (int)e.x; d[1] = (int)e.y; d[2] = (int)f.x; d[3] = (int)f.y;
                } else {
                    int4 a = __ldg((const int4*)(ei32 + base));
                    int4 c = __ldg((const int4*)(ei32 + E + base));
                    s[0] = a.x; s[1] = a.y; s[2] = a.z; s[3] = a.w;
                    d[0] = c.x; d[1] = c.y; d[2] = c.z; d[3] = c.w;
                }
                #pragma unroll
                for (int k = 0; k < 4; k++) {
                    s[k] = min(max(s[k], 0), N - 1);
                    d[k] = min(max(d[k], 0), N - 1);
                }
                ((int4*)g_EDGE)[(base >> 1)]     = make_int4(s[0], d[0], s[1], d[1]);
                ((int4*)g_EDGE)[(base >> 1) + 1] = make_int4(s[2], d[2], s[3], d[3]);
            } else {
                for (long long e = base; e < E; e++) {
                    int src, dst;
                    if (is64) {
                        src = (int)((const long long*)ei32)[e];
                        dst = (int)((const long long*)ei32)[E + e];
                    } else {
                        src = ei32[e]; dst = ei32[E + e];
                    }
                    g_EDGE[e] = make_int2(min(max(src, 0), N - 1),
                                          min(max(dst, 0), N - 1));
                }
            }
        }
        cudaTriggerProgrammaticLaunchCompletion();
        return;
    }

    // -------- remaining blocks: passA (half-warp per node) --------
    int ab   = b - 1 - decBlocks;
    int node = ab * 16 + (t >> 4);
    int lane = t & 15;

    // issue x load BEFORE waiting for prep (hide prep latency behind DRAM read)
    float4 xv = make_float4(0.f, 0.f, 0.f, 0.f);
    if (node < N) xv = __ldg(((const float4*)x) + (long long)node * 16 + lane);

    if (t == 0) {
        while (*(volatile int*)&g_ready == 0) { __nanosleep(64); }
        __threadfence();
    }
    __syncthreads();

    if (node < N) {
        float4 pv = ((const float4*)g_P)[lane];
        float4 gv = ((const float4*)g_G)[lane];
        float4 sv = ((const float4*)g_S)[lane];

        float xp = xv.x * pv.x + xv.y * pv.y + xv.z * pv.z + xv.w * pv.w;
        float xg = xv.x * gv.x + xv.y * gv.y + xv.z * gv.z + xv.w * gv.w;
        float xs = xv.x * sv.x + xv.y * sv.y + xv.z * sv.z + xv.w * sv.w;

        #pragma unroll
        for (int off = 8; off; off >>= 1) {
            xp += __shfl_xor_sync(0xffffffffu, xp, off);
            xg += __shfl_xor_sync(0xffffffffu, xg, off);
            xs += __shfl_xor_sync(0xffffffffu, xs, off);
        }
        if (lane == 0) {
            g_XPG[node] = make_float2(xp, xg);
            g_ACC[node] = make_float4(0.f, 0.f, 0.f, xs);
            g_SB[node]  = 0.f;
        }
    }
    cudaTriggerProgrammaticLaunchCompletion();
}

// ===================== scatter 1: ACC[dst] += (xp, 1, xg, 0) =====================
// one-wave grid (SBLK blocks), grid-stride over 4-edge chunks
__global__ void __launch_bounds__(256) k_scatter1(int E)
{
    cudaGridDependencySynchronize();

    const long long T4 = (long long)SBLK * 256 * 4;
    for (long long base = (long long)(blockIdx.x * 256 + threadIdx.x) * 4;
         base < E; base += T4) {
        if (base + 3 < E) {
            int4 q0 = ((const int4*)g_EDGE)[base >> 1];        // (s0,d0,s1,d1)
            int4 q1 = ((const int4*)g_EDGE)[(base >> 1) + 1];  // (s2,d2,s3,d3)
            float2 v0 = __ldg(&g_XPG[q0.x]);
            float2 v1 = __ldg(&g_XPG[q0.z]);
            float2 v2 = __ldg(&g_XPG[q1.x]);
            float2 v3 = __ldg(&g_XPG[q1.z]);
            atomicAdd(&g_ACC[q0.y], make_float4(v0.x, 1.f, v0.y, 0.f));
            atomicAdd(&g_ACC[q0.w], make_float4(v1.x, 1.f, v1.y, 0.f));
            atomicAdd(&g_ACC[q1.y], make_float4(v2.x, 1.f, v2.y, 0.f));
            atomicAdd(&g_ACC[q1.w], make_float4(v3.x, 1.f, v3.y, 0.f));
        } else {
            for (long long e = base; e < E; e++) {
                int2 ed = g_EDGE[e];
                float2 v = __ldg(&g_XPG[ed.x]);
                atomicAdd(&g_ACC[ed.y], make_float4(v.x, 1.f, v.y, 0.f));
            }
        }
    }
    cudaTriggerProgrammaticLaunchCompletion();
}

// ===================== scatter 2 + fused final (last block) =====================
__global__ void __launch_bounds__(256) k_scatter2(float* __restrict__ out,
                                                  int N, int E)
{
    cudaGridDependencySynchronize();

    const long long T4 = (long long)SBLK * 256 * 4;
    for (long long base = (long long)(blockIdx.x * 256 + threadIdx.x) * 4;
         base < E; base += T4) {
        if (base + 3 < E) {
            int4 q0 = ((const int4*)g_EDGE)[base >> 1];
            int4 q1 = ((const int4*)g_EDGE)[(base >> 1) + 1];
            float2 a0 = __ldg((const float2*)&g_ACC[q0.x]);    // (SA, deg)
            float2 a1 = __ldg((const float2*)&g_ACC[q0.z]);
            float2 a2 = __ldg((const float2*)&g_ACC[q1.x]);
            float2 a3 = __ldg((const float2*)&g_ACC[q1.z]);
            atomicAdd(&g_SB[q0.y], a0.x * __frcp_rn(fmaxf(a0.y, 1.f)));
            atomicAdd(&g_SB[q0.w], a1.x * __frcp_rn(fmaxf(a1.y, 1.f)));
            atomicAdd(&g_SB[q1.y], a2.x * __frcp_rn(fmaxf(a2.y, 1.f)));
            atomicAdd(&g_SB[q1.w], a3.x * __frcp_rn(fmaxf(a3.y, 1.f)));
        } else {
            for (long long e = base; e < E; e++) {
                int2 ed = g_EDGE[e];
                float2 a = __ldg((const float2*)&g_ACC[ed.x]);
                atomicAdd(&g_SB[ed.y], a.x * __frcp_rn(fmaxf(a.y, 1.f)));
            }
        }
    }

    // ---- last-block-done: the final finishing block computes out[] ----
    __threadfence();                       // make this block's REDs visible
    __syncthreads();
    __shared__ int s_last;
    if (threadIdx.x == 0) {
        unsigned ticket = atomicAdd(&g_done, 1u);
        s_last = (ticket == (unsigned)gridDim.x - 1u);
        if (s_last) g_done = 0;            // reset for next graph replay
    }
    __syncthreads();
    if (!s_last) return;

    __threadfence();                       // acquire all blocks' REDs
    float cb = g_C[0], c2 = g_C[1];
    // 4-node batches per thread for MLP
    for (int i0 = threadIdx.x * 4; i0 < N; i0 += 256 * 4) {
        float4 a[4];
        float  sb[4];
        #pragma unroll
        for (int k = 0; k < 4; k++) {
            int i = i0 + k;
            if (i < N) { a[k] = g_ACC[i]; sb[k] = g_SB[i]; }
        }
        #pragma unroll
        for (int k = 0; k < 4; k++) {
            int i = i0 + k;
            if (i < N) {
                float inv = __frcp_rn(fmaxf(a[k].y, 1.f));
                float res = inv * (sb[k] + a[k].z) + a[k].w + c2;
                if (a[k].y > 0.f) res += cb;
                out[i] = res;
            }
        }
    }
}

// ===================== launch =====================
extern "C" void kernel_launch(void* const* d_in, const int* in_sizes, int n_in,
                              void* d_out, int out_size)
{
    const float* x    = (const float*)d_in[0];
    const int*   ei32 = (const int*)d_in[1];
    // d_in[2] = edge_weight (unused by the reference)
    const float* Wl1  = (const float*)d_in[3];
    const float* Wr1  = (const float*)d_in[4];
    const float* b1   = (const float*)d_in[5];
    const float* Wl2  = (const float*)d_in[6];
    const float* Wr2  = (const float*)d_in[7];
    const float* b2   = (const float*)d_in[8];
    const float* Wfc1 = (const float*)d_in[9];
    const float* bfc1 = (const float*)d_in[10];
    const float* Wfc2 = (const float*)d_in[11];
    const float* bfc2 = (const float*)d_in[12];
    float* out = (float*)d_out;

    int N = in_sizes[0] / NFEAT;   // 100000
    int E = in_sizes[2];           // 1600000

    int decB = (E + 1023) / 1024;          // decode blocks (4 edges/thread)
    int aB   = (N + 15) / 16;              // passA blocks (16 nodes/block)

    k_init<<<1 + decB + aB, 256>>>(x, ei32, Wl1, Wr1, b1, Wl2, Wr2, b2,
                                   Wfc1, bfc1, Wfc2, bfc2, N, E, decB);

    cudaLaunchAttribute at[1];
    at[0].id = cudaLaunchAttributeProgrammaticStreamSerialization;
    at[0].val.programmaticStreamSerializationAllowed = 1;

    cudaLaunchConfig_t cfg = {};
    cfg.blockDim = dim3(256, 1, 1);
    cfg.gridDim  = dim3(SBLK, 1, 1);
    cfg.attrs    = at;
    cfg.numAttrs = 1;
    cfg.stream   = 0;

    cudaLaunchKernelEx(&cfg, k_scatter1, E);
    cudaLaunchKernelEx(&cfg, k_scatter2, out, N, E);
}

// round 14
// speedup vs baseline: 1.9454x; 1.9454x over previous
#include <cuda_runtime.h>

// GCN_18760417149681 — fully linear GraphSAGE collapse, v14 = R11 + warp-parallel
// dtype sniff (the serial 32-load sniff in thread0 cost ~10us PER decode block).
// out[m] = inv[m]*(SB[m] + SG[m]) + xs[m] + (deg[m]>0)*CB + C2
//   ACC[m] = (SA, deg, SG, xs);  scatter1: ACC[dst] += (xp[src], 1, xg[src], 0)
//   scatter2: SB[dst] += SA[src]/max(deg[src],1)
// Four kernels chained with programmatic dependent launch.

#define NMAX  100000
#define EMAX  1600000
#define NFEAT 64
#define NHID  128

__device__ __align__(16) float g_P[NFEAT];
__device__ __align__(16) float g_G[NFEAT];
__device__ __align__(16) float g_S[NFEAT];
__device__ float g_C[2];        // [0]=cb (gated by deg>0), [1]=c2
__device__ int   g_ready = 0;   // prep-done flag (rewrites value-identical)

__device__ __align__(16) float4 g_ACC[NMAX];   // (SA, deg, SG, xs)
__device__ __align__(8)  float2 g_XPG[NMAX];   // (xp, xg)
__device__ float g_SB[NMAX];
__device__ __align__(16) int2  g_EDGE[EMAX];   // packed (src, dst)

// ---- warp-parallel dtype sniff: 32 lanes load one odd 32-bit word each.
// int64 LE with small indices => all odd words zero. ~1 memory latency total.
__device__ __forceinline__ int sniff_is64_warp(const int* __restrict__ ei32, int E)
{
    int lane = threadIdx.x & 31;
    long long pos = (1 + (long long)lane * ((2LL * E - 2) / 32)) | 1;
    unsigned nz = __ballot_sync(0xffffffffu, ei32[pos] != 0);
    return (nz == 0u) ? 1 : 0;
}

// ===================== launch 1: prep + decode + passA =====================
__global__ void __launch_bounds__(256) k_init(
    const float* __restrict__ x, const int* __restrict__ ei32,
    const float* __restrict__ Wl1, const float* __restrict__ Wr1,
    const float* __restrict__ b1,
    const float* __restrict__ Wl2, const float* __restrict__ Wr2,
    const float* __restrict__ b2,
    const float* __restrict__ Wfc1, const float* __restrict__ bfc1,
    const float* __restrict__ Wfc2, const float* __restrict__ bfc2,
    int N, int E, int decBlocks)
{
    int b = blockIdx.x;
    int t = threadIdx.x;

    // -------- block 0: weight collapse --------
    if (b == 0) {
        __shared__ float sw[NHID], su[NHID], sv[NHID];
        if (t < NHID) {
            float acc = 0.f;
            #pragma unroll
            for (int c = 0; c < 32; c++) acc += Wfc1[t * 32 + c] * Wfc2[c];
            sw[t] = acc;
        }
        __syncthreads();
        if (t < NHID) {
            float au = 0.f, av = 0.f;
            #pragma unroll 4
            for (int j = 0; j < NHID; j++) {
                float wv = sw[j];
                au += Wl2[t * NHID + j] * wv;
                av += Wr2[t * NHID + j] * wv;
            }
            su[t] = au; sv[t] = av;
        }
        __syncthreads();
        if (t < NFEAT) {
            float p = 0.f, g = 0.f, s = 0.f;
            #pragma unroll 4
            for (int j = 0; j < NHID; j++) {
                float wl = Wl1[t * NHID + j];
                float wr = Wr1[t * NHID + j];
                float uj = su[j], vj = sv[j];
                p += wl * uj;
                g += wr * uj + wl * vj;
                s += wr * vj;
            }
            g_P[t] = p; g_G[t] = g; g_S[t] = s;
        }
        if (t == 0) {
            float cb = 0.f, c2 = 0.f;
            for (int j = 0; j < NHID; j++) {
                cb += b1[j] * su[j];
                c2 += b1[j] * sv[j] + b2[j] * sw[j];
            }
            for (int c = 0; c < 32; c++) c2 += bfc1[c] * Wfc2[c];
            c2 += bfc2[0];
            g_C[0] = cb; g_C[1] = c2;
        }
        __syncthreads();
        if (t == 0) {
            __threadfence();                 // release g_P/g_G/g_S/g_C
            atomicExch(&g_ready, 1);
        }
        cudaTriggerProgrammaticLaunchCompletion();
        return;
    }

    // -------- blocks [1, decBlocks]: edge decode to packed int2 --------
    if (b <= decBlocks) {
        __shared__ int s_is64;
        if (t < 32) {
            int is = sniff_is64_warp(ei32, E);
            if (t == 0) s_is64 = is;
        }
        __syncthreads();
        int is64 = s_is64;

        long long base = ((long long)(b - 1) * 256 + t) * 4;
        if (base < E) {
            if (base + 3 < E) {
                int s[4], d[4];
                if (is64) {
                    const long long* p = (const long long*)ei32;
                    longlong2 a = __ldg((const longlong2*)(p + base));
                    longlong2 c = __ldg((const longlong2*)(p + base + 2));
                    longlong2 e = __ldg((const longlong2*)(p + E + base));
                    longlong2 f = __ldg((const longlong2*)(p + E + base + 2));
                    s[0] = (int)a.x; s[1] = (int)a.y; s[2] = (int)c.x; s[3] = (int)c.y;
                    d[0] = (int)e.x; d[1] = (int)e.y; d[2] = (int)f.x; d[3] = (int)f.y;
                } else {
                    int4 a = __ldg((const int4*)(ei32 + base));
                    int4 c = __ldg((const int4*)(ei32 + E + base));
                    s[0] = a.x; s[1] = a.y; s[2] = a.z; s[3] = a.w;
                    d[0] = c.x; d[1] = c.y; d[2] = c.z; d[3] = c.w;
                }
                #pragma unroll
                for (int k = 0; k < 4; k++) {
                    s[k] = min(max(s[k], 0), N - 1);
                    d[k] = min(max(d[k], 0), N - 1);
                }
                ((int4*)g_EDGE)[(base >> 1)]     = make_int4(s[0], d[0], s[1], d[1]);
                ((int4*)g_EDGE)[(base >> 1) + 1] = make_int4(s[2], d[2], s[3], d[3]);
            } else {
                for (long long e = base; e < E; e++) {
                    int src, dst;
                    if (is64) {
                        src = (int)((const long long*)ei32)[e];
                        dst = (int)((const long long*)ei32)[E + e];
                    } else {
                        src = ei32[e]; dst = ei32[E + e];
                    }
                    src = min(max(src, 0), N - 1);
                    dst = min(max(dst, 0), N - 1);
                    g_EDGE[e] = make_int2(src, dst);
                }
            }
        }
        cudaTriggerProgrammaticLaunchCompletion();
        return;
    }

    // -------- remaining blocks: passA (half-warp per node) --------
    if (t == 0) {
        while (*(volatile int*)&g_ready == 0) { __nanosleep(64); }
        __threadfence();                     // acquire
    }
    __syncthreads();

    int ab   = b - 1 - decBlocks;
    int node = ab * 16 + (t >> 4);
    int lane = t & 15;
    if (node < N) {
        float4 xv = __ldg(((const float4*)x) + (long long)node * 16 + lane);
        float4 pv = ((const float4*)g_P)[lane];
        float4 gv = ((const float4*)g_G)[lane];
        float4 sv = ((const float4*)g_S)[lane];

        float xp = xv.x * pv.x + xv.y * pv.y + xv.z * pv.z + xv.w * pv.w;
        float xg = xv.x * gv.x + xv.y * gv.y + xv.z * gv.z + xv.w * gv.w;
        float xs = xv.x * sv.x + xv.y * sv.y + xv.z * sv.z + xv.w * sv.w;

        #pragma unroll
        for (int off = 8; off; off >>= 1) {
            xp += __shfl_xor_sync(0xffffffffu, xp, off);
            xg += __shfl_xor_sync(0xffffffffu, xg, off);
            xs += __shfl_xor_sync(0xffffffffu, xs, off);
        }
        if (lane == 0) {
            g_XPG[node] = make_float2(xp, xg);
            g_ACC[node] = make_float4(0.f, 0.f, 0.f, xs);
            g_SB[node]  = 0.f;
        }
    }
    cudaTriggerProgrammaticLaunchCompletion();
}

// ===================== scatter 1: ACC[dst] += (xp, 1, xg, 0) =====================
__global__ void __launch_bounds__(256) k_scatter1(int E)
{
    cudaGridDependencySynchronize();

    long long base = (long long)(blockIdx.x * 256 + threadIdx.x) * 4;
    if (base < E) {
        if (base + 3 < E) {
            int4 q0 = ((const int4*)g_EDGE)[base >> 1];        // (s0,d0,s1,d1)
            int4 q1 = ((const int4*)g_EDGE)[(base >> 1) + 1];  // (s2,d2,s3,d3)
            float2 v0 = __ldg(&g_XPG[q0.x]);
            float2 v1 = __ldg(&g_XPG[q0.z]);
            float2 v2 = __ldg(&g_XPG[q1.x]);
            float2 v3 = __ldg(&g_XPG[q1.z]);
            atomicAdd(&g_ACC[q0.y], make_float4(v0.x, 1.f, v0.y, 0.f));
            atomicAdd(&g_ACC[q0.w], make_float4(v1.x, 1.f, v1.y, 0.f));
            atomicAdd(&g_ACC[q1.y], make_float4(v2.x, 1.f, v2.y, 0.f));
            atomicAdd(&g_ACC[q1.w], make_float4(v3.x, 1.f, v3.y, 0.f));
        } else {
            for (long long e = base; e < E; e++) {
                int2 ed = g_EDGE[e];
                float2 v = __ldg(&g_XPG[ed.x]);
                atomicAdd(&g_ACC[ed.y], make_float4(v.x, 1.f, v.y, 0.f));
            }
        }
    }
    cudaTriggerProgrammaticLaunchCompletion();
}

// ===================== scatter 2: SB[dst] += SA[src]/max(deg,1) ==============
__global__ void __launch_bounds__(256) k_scatter2(int E)
{
    cudaGridDependencySynchronize();

    long long base = (long long)(blockIdx.x * 256 + threadIdx.x) * 4;
    if (base < E) {
        if (base + 3 < E) {
            int4 q0 = ((const int4*)g_EDGE)[base >> 1];
            int4 q1 = ((const int4*)g_EDGE)[(base >> 1) + 1];
            float2 a0 = __ldg((const float2*)&g_ACC[q0.x]);    // (SA, deg)
            float2 a1 = __ldg((const float2*)&g_ACC[q0.z]);
            float2 a2 = __ldg((const float2*)&g_ACC[q1.x]);
            float2 a3 = __ldg((const float2*)&g_ACC[q1.z]);
            atomicAdd(&g_SB[q0.y], a0.x * __frcp_rn(fmaxf(a0.y, 1.f)));
            atomicAdd(&g_SB[q0.w], a1.x * __frcp_rn(fmaxf(a1.y, 1.f)));
            atomicAdd(&g_SB[q1.y], a2.x * __frcp_rn(fmaxf(a2.y, 1.f)));
            atomicAdd(&g_SB[q1.w], a3.x * __frcp_rn(fmaxf(a3.y, 1.f)));
        } else {
            for (long long e = base; e < E; e++) {
                int2 ed = g_EDGE[e];
                float2 a = __ldg((const float2*)&g_ACC[ed.x]);
                atomicAdd(&g_SB[ed.y], a.x * __frcp_rn(fmaxf(a.y, 1.f)));
            }
        }
    }
    cudaTriggerProgrammaticLaunchCompletion();
}

// ===================== final =====================
__global__ void __launch_bounds__(256) k_final(float* __restrict__ out, int n)
{
    cudaGridDependencySynchronize();

    int i = blockIdx.x * blockDim.x + threadIdx.x;
    if (i < n) {
        float cb = g_C[0], c2 = g_C[1];
        float4 a = g_ACC[i];                 // (SA, deg, SG, xs)
        float inv = __frcp_rn(fmaxf(a.y, 1.f));
        float res = inv * (g_SB[i] + a.z) + a.w + c2;
        if (a.y > 0.f) res += cb;
        out[i] = res;
    }
}

// ===================== launch =====================
extern "C" void kernel_launch(void* const* d_in, const int* in_sizes, int n_in,
                              void* d_out, int out_size)
{
    const float* x    = (const float*)d_in[0];
    const int*   ei32 = (const int*)d_in[1];
    // d_in[2] = edge_weight (unused by the reference)
    const float* Wl1  = (const float*)d_in[3];
    const float* Wr1  = (const float*)d_in[4];
    const float* b1   = (const float*)d_in[5];
    const float* Wl2  = (const float*)d_in[6];
    const float* Wr2  = (const float*)d_in[7];
    const float* b2   = (const float*)d_in[8];
    const float* Wfc1 = (const float*)d_in[9];
    const float* bfc1 = (const float*)d_in[10];
    const float* Wfc2 = (const float*)d_in[11];
    const float* bfc2 = (const float*)d_in[12];
    float* out = (float*)d_out;

    int N = in_sizes[0] / NFEAT;   // 100000
    int E = in_sizes[2];           // 1600000

    int decB = (E + 1023) / 1024;          // decode blocks (4 edges/thread)
    int aB   = (N + 15) / 16;              // passA blocks (16 nodes/block)
    int eB   = decB;                       // scatter blocks (4 edges/thread)
    int fB   = (N + 255) / 256;

    // first kernel: plain launch
    k_init<<<1 + decB + aB, 256>>>(x, ei32, Wl1, Wr1, b1, Wl2, Wr2, b2,
                                   Wfc1, bfc1, Wfc2, bfc2, N, E, decB);

    // successors: programmatic dependent launch
    cudaLaunchAttribute at[1];
    at[0].id = cudaLaunchAttributeProgrammaticStreamSerialization;
    at[0].val.programmaticStreamSerializationAllowed = 1;

    cudaLaunchConfig_t cfg = {};
    cfg.blockDim = dim3(256, 1, 1);
    cfg.attrs    = at;
    cfg.numAttrs = 1;
    cfg.stream   = 0;

    cfg.gridDim = dim3(eB, 1, 1);
    cudaLaunchKernelEx(&cfg, k_scatter1, E);

    cfg.gridDim = dim3(eB, 1, 1);
    cudaLaunchKernelEx(&cfg, k_scatter2, E);

    cfg.gridDim = dim3(fB, 1, 1);
    cudaLaunchKernelEx(&cfg, k_final, out, N);
}

// round 15
// speedup vs baseline: 1.9870x; 1.0214x over previous
#include <cuda_runtime.h>

// GCN_18760417149681 — fully linear GraphSAGE collapse, v15.
// Decode pass REMOVED (net LSU-op reduction); scatters read raw int32/int64
// indices with a warp-parallel dtype sniff (R12's regression traced to its
// serial per-block sniff bubble, not index width).
// out[m] = inv[m]*(SB[m] + SG[m]) + xs[m] + (deg[m]>0)*CB + C2
//   ACC[m] = (SA, deg, SG, xs);  scatter1: ACC[dst] += (xp[src], 1, xg[src], 0)
//   scatter2: SB[dst] += SA[src]/max(deg[src],1)
// k_init = prep(block0) + passA. PDL chains the 4 kernels.

#define NMAX  100000
#define NFEAT 64
#define NHID  128

__device__ __align__(16) float g_P[NFEAT];
__device__ __align__(16) float g_G[NFEAT];
__device__ __align__(16) float g_S[NFEAT];
__device__ float g_C[2];        // [0]=cb (gated by deg>0), [1]=c2
__device__ int   g_ready = 0;   // prep-done flag (rewrites value-identical)

__device__ __align__(16) float4 g_ACC[NMAX];   // (SA, deg, SG, xs)
__device__ __align__(8)  float2 g_XPG[NMAX];   // (xp, xg)
__device__ float g_SB[NMAX];

// ---- warp-parallel dtype sniff: 32 lanes load one odd 32-bit word each.
// int64 LE with small indices => all odd words zero. One memory latency.
__device__ __forceinline__ int sniff_is64_warp(const int* __restrict__ ei32, int E)
{
    int lane = threadIdx.x & 31;
    long long pos = (1 + (long long)lane * ((2LL * E - 2) / 32)) | 1;
    unsigned nz = __ballot_sync(0xffffffffu, ei32[pos] != 0);
    return (nz == 0u) ? 1 : 0;
}

// ---- load 4 edges (src,dst) from raw indices, clamped ----
__device__ __forceinline__ void load4raw(const int* __restrict__ ei32, long long E,
                                         long long base, int is64, int N,
                                         int (&s)[4], int (&d)[4])
{
    if (is64) {
        const long long* p = (const long long*)ei32;
        longlong2 a0 = __ldg((const longlong2*)(p + base));
        longlong2 a1 = __ldg((const longlong2*)(p + base + 2));
        longlong2 c0 = __ldg((const longlong2*)(p + E + base));
        longlong2 c1 = __ldg((const longlong2*)(p + E + base + 2));
        s[0] = (int)a0.x; s[1] = (int)a0.y; s[2] = (int)a1.x; s[3] = (int)a1.y;
        d[0] = (int)c0.x; d[1] = (int)c0.y; d[2] = (int)c1.x; d[3] = (int)c1.y;
    } else {
        int4 a = __ldg((const int4*)(ei32 + base));
        int4 c = __ldg((const int4*)(ei32 + E + base));
        s[0] = a.x; s[1] = a.y; s[2] = a.z; s[3] = a.w;
        d[0] = c.x; d[1] = c.y; d[2] = c.z; d[3] = c.w;
    }
    #pragma unroll
    for (int k = 0; k < 4; k++) {
        s[k] = min(max(s[k], 0), N - 1);
        d[k] = min(max(d[k], 0), N - 1);
    }
}

// ===================== launch 1: prep (block 0) + passA =====================
__global__ void __launch_bounds__(256) k_init(
    const float* __restrict__ x,
    const float* __restrict__ Wl1, const float* __restrict__ Wr1,
    const float* __restrict__ b1,
    const float* __restrict__ Wl2, const float* __restrict__ Wr2,
    const float* __restrict__ b2,
    const float* __restrict__ Wfc1, const float* __restrict__ bfc1,
    const float* __restrict__ Wfc2, const float* __restrict__ bfc2,
    int N)
{
    int b = blockIdx.x;
    int t = threadIdx.x;

    if (b == 0) {
        __shared__ float sw[NHID], su[NHID], sv[NHID];
        if (t < NHID) {
            float acc = 0.f;
            #pragma unroll
            for (int c = 0; c < 32; c++) acc += Wfc1[t * 32 + c] * Wfc2[c];
            sw[t] = acc;
        }
        __syncthreads();
        if (t < NHID) {
            float au = 0.f, av = 0.f;
            #pragma unroll 4
            for (int j = 0; j < NHID; j++) {
                float wv = sw[j];
                au += Wl2[t * NHID + j] * wv;
                av += Wr2[t * NHID + j] * wv;
            }
            su[t] = au; sv[t] = av;
        }
        __syncthreads();
        if (t < NFEAT) {
            float p = 0.f, g = 0.f, s = 0.f;
            #pragma unroll 4
            for (int j = 0; j < NHID; j++) {
                float wl = Wl1[t * NHID + j];
                float wr = Wr1[t * NHID + j];
                float uj = su[j], vj = sv[j];
                p += wl * uj;
                g += wr * uj + wl * vj;
                s += wr * vj;
            }
            g_P[t] = p; g_G[t] = g; g_S[t] = s;
        }
        if (t == 0) {
            float cb = 0.f, c2 = 0.f;
            for (int j = 0; j < NHID; j++) {
                cb += b1[j] * su[j];
                c2 += b1[j] * sv[j] + b2[j] * sw[j];
            }
            for (int c = 0; c < 32; c++) c2 += bfc1[c] * Wfc2[c];
            c2 += bfc2[0];
            g_C[0] = cb; g_C[1] = c2;
        }
        __syncthreads();
        if (t == 0) {
            __threadfence();                 // release g_P/g_G/g_S/g_C
            atomicExch(&g_ready, 1);
        }
        cudaTriggerProgrammaticLaunchCompletion();
        return;
    }

    // -------- passA blocks (half-warp per node); wait for prep --------
    if (t == 0) {
        while (*(volatile int*)&g_ready == 0) { __nanosleep(64); }
        __threadfence();                     // acquire
    }
    __syncthreads();

    int node = (b - 1) * 16 + (t >> 4);
    int lane = t & 15;
    if (node < N) {
        float4 xv = __ldg(((const float4*)x) + (long long)node * 16 + lane);
        float4 pv = ((const float4*)g_P)[lane];
        float4 gv = ((const float4*)g_G)[lane];
        float4 sv = ((const float4*)g_S)[lane];

        float xp = xv.x * pv.x + xv.y * pv.y + xv.z * pv.z + xv.w * pv.w;
        float xg = xv.x * gv.x + xv.y * gv.y + xv.z * gv.z + xv.w * gv.w;
        float xs = xv.x * sv.x + xv.y * sv.y + xv.z * sv.z + xv.w * sv.w;

        #pragma unroll
        for (int off = 8; off; off >>= 1) {
            xp += __shfl_xor_sync(0xffffffffu, xp, off);
            xg += __shfl_xor_sync(0xffffffffu, xg, off);
            xs += __shfl_xor_sync(0xffffffffu, xs, off);
        }
        if (lane == 0) {
            g_XPG[node] = make_float2(xp, xg);
            g_ACC[node] = make_float4(0.f, 0.f, 0.f, xs);
            g_SB[node]  = 0.f;
        }
    }
    cudaTriggerProgrammaticLaunchCompletion();
}

// ===================== scatter 1: ACC[dst] += (xp, 1, xg, 0) =====================
__global__ void __launch_bounds__(256) k_scatter1(const int* __restrict__ ei32,
                                                  int N, int E)
{
    __shared__ int s_is64;
    if (threadIdx.x < 32) {
        int is = sniff_is64_warp(ei32, E);   // warp-parallel: one mem latency
        if (threadIdx.x == 0) s_is64 = is;
    }
    cudaGridDependencySynchronize();
    __syncthreads();
    int is64 = s_is64;

    long long base = (long long)(blockIdx.x * 256 + threadIdx.x) * 4;
    if (base < E) {
        if (base + 3 < E) {
            int s[4], d[4];
            load4raw(ei32, E, base, is64, N, s, d);
            float2 v0 = __ldg(&g_XPG[s[0]]);
            float2 v1 = __ldg(&g_XPG[s[1]]);
            float2 v2 = __ldg(&g_XPG[s[2]]);
            float2 v3 = __ldg(&g_XPG[s[3]]);
            atomicAdd(&g_ACC[d[0]], make_float4(v0.x, 1.f, v0.y, 0.f));
            atomicAdd(&g_ACC[d[1]], make_float4(v1.x, 1.f, v1.y, 0.f));
            atomicAdd(&g_ACC[d[2]], make_float4(v2.x, 1.f, v2.y, 0.f));
            atomicAdd(&g_ACC[d[3]], make_float4(v3.x, 1.f, v3.y, 0.f));
        } else {
            for (long long e = base; e < E; e++) {
                int src, dst;
                if (is64) {
                    src = (int)((const long long*)ei32)[e];
                    dst = (int)((const long long*)ei32)[E + e];
                } else {
                    src = ei32[e]; dst = ei32[E + e];
                }
                src = min(max(src, 0), N - 1);
                dst = min(max(dst, 0), N - 1);
                float2 v = __ldg(&g_XPG[src]);
                atomicAdd(&g_ACC[dst], make_float4(v.x, 1.f, v.y, 0.f));
            }
        }
    }
    cudaTriggerProgrammaticLaunchCompletion();
}

// ===================== scatter 2: SB[dst] += SA[src]/max(deg,1) ==============
__global__ void __launch_bounds__(256) k_scatter2(const int* __restrict__ ei32,
                                                  int N, int E)
{
    __shared__ int s_is64;
    if (threadIdx.x < 32) {
        int is = sniff_is64_warp(ei32, E);
        if (threadIdx.x == 0) s_is64 = is;
    }
    cudaGridDependencySynchronize();
    __syncthreads();
    int is64 = s_is64;

    long long base = (long long)(blockIdx.x * 256 + threadIdx.x) * 4;
    if (base < E) {
        if (base + 3 < E) {
            int s[4], d[4];
            load4raw(ei32, E, base, is64, N, s, d);
            float2 a0 = __ldg((const float2*)&g_ACC[s[0]]);    // (SA, deg)
            float2 a1 = __ldg((const float2*)&g_ACC[s[1]]);
            float2 a2 = __ldg((const float2*)&g_ACC[s[2]]);
            float2 a3 = __ldg((const float2*)&g_ACC[s[3]]);
            atomicAdd(&g_SB[d[0]], a0.x * __frcp_rn(fmaxf(a0.y, 1.f)));
            atomicAdd(&g_SB[d[1]], a1.x * __frcp_rn(fmaxf(a1.y, 1.f)));
            atomicAdd(&g_SB[d[2]], a2.x * __frcp_rn(fmaxf(a2.y, 1.f)));
            atomicAdd(&g_SB[d[3]], a3.x * __frcp_rn(fmaxf(a3.y, 1.f)));
        } else {
            for (long long e = base; e < E; e++) {
                int src, dst;
                if (is64) {
                    src = (int)((const long long*)ei32)[e];
                    dst = (int)((const long long*)ei32)[E + e];
                } else {
                    src = ei32[e]; dst = ei32[E + e];
                }
                src = min(max(src, 0), N - 1);
                dst = min(max(dst, 0), N - 1);
                float2 a = __ldg((const float2*)&g_ACC[src]);
                atomicAdd(&g_SB[dst], a.x * __frcp_rn(fmaxf(a.y, 1.f)));
            }
        }
    }
    cudaTriggerProgrammaticLaunchCompletion();
}

// ===================== final =====================
__global__ void __launch_bounds__(256) k_final(float* __restrict__ out, int n)
{
    cudaGridDependencySynchronize();

    int i = blockIdx.x * blockDim.x + threadIdx.x;
    if (i < n) {
        float cb = g_C[0], c2 = g_C[1];
        float4 a = g_ACC[i];                 // (SA, deg, SG, xs)
        float inv = __frcp_rn(fmaxf(a.y, 1.f));
        float res = inv * (g_SB[i] + a.z) + a.w + c2;
        if (a.y > 0.f) res += cb;
        out[i] = res;
    }
}

// ===================== launch =====================
extern "C" void kernel_launch(void* const* d_in, const int* in_sizes, int n_in,
                              void* d_out, int out_size)
{
    const float* x    = (const float*)d_in[0];
    const int*   ei32 = (const int*)d_in[1];
    // d_in[2] = edge_weight (unused by the reference)
    const float* Wl1  = (const float*)d_in[3];
    const float* Wr1  = (const float*)d_in[4];
    const float* b1   = (const float*)d_in[5];
    const float* Wl2  = (const float*)d_in[6];
    const float* Wr2  = (const float*)d_in[7];
    const float* b2   = (const float*)d_in[8];
    const float* Wfc1 = (const float*)d_in[9];
    const float* bfc1 = (const float*)d_in[10];
    const float* Wfc2 = (const float*)d_in[11];
    const float* bfc2 = (const float*)d_in[12];
    float* out = (float*)d_out;

    int N = in_sizes[0] / NFEAT;   // 100000
    int E = in_sizes[2];           // 1600000

    int aB = (N + 15) / 16;                // passA blocks (16 nodes/block)
    int eB = (E + 1023) / 1024;            // scatter blocks (4 edges/thread)
    int fB = (N + 255) / 256;

    k_init<<<1 + aB, 256>>>(x, Wl1, Wr1, b1, Wl2, Wr2, b2,
                            Wfc1, bfc1, Wfc2, bfc2, N);

    cudaLaunchAttribute at[1];
    at[0].id = cudaLaunchAttributeProgrammaticStreamSerialization;
    at[0].val.programmaticStreamSerializationAllowed = 1;

    cudaLaunchConfig_t cfg = {};
    cfg.blockDim = dim3(256, 1, 1);
    cfg.attrs    = at;
    cfg.numAttrs = 1;
    cfg.stream   = 0;

    cfg.gridDim = dim3(eB, 1, 1);
    cudaLaunchKernelEx(&cfg, k_scatter1, ei32, N, E);

    cfg.gridDim = dim3(eB, 1, 1);
    cudaLaunchKernelEx(&cfg, k_scatter2, ei32, N, E);

    cfg.gridDim = dim3(fB, 1, 1);
    cudaLaunchKernelEx(&cfg, k_final, out, N);
}